// round 2
// baseline (speedup 1.0000x reference)
#include <cuda_runtime.h>
#include <cstdint>

// Problem constants
#define B_WIN   1024
#define LTOK    49
#define CDIM    384
#define HEADS   12
#define HD      32
#define NWMASK  4
#define MTOT    (B_WIN * LTOK)          // 50176
#define QKVN    (3 * CDIM)              // 1152
#define SCALE_F 19.595917942265426f     // sqrt(384)

// Scratch (device globals: allocation-free per harness rules)
__device__ __align__(16) float g_qkv[(size_t)MTOT * QKVN];   // 231 MB
__device__ __align__(16) float g_o[(size_t)MTOT * CDIM];     // 77 MB
__device__ __align__(16) float g_bias[HEADS * LTOK * LTOK];  // 12*2401
__device__ unsigned long long g_maskbits[NWMASK * LTOK];     // 196

// ---------------------------------------------------------------------------
// Prep: detect mask dtype, build bitmasks, gather relative-position bias
// mask has NW*L*L = 9604 elements. As u8 that's exactly 2401 32-bit words, so
// scanning the first 2401 words is safe for every candidate dtype.
// ---------------------------------------------------------------------------
__global__ void prep_kernel(const void* __restrict__ mask_raw,
                            const float* __restrict__ rel_bias,
                            const int* __restrict__ rel_coords)
{
    __shared__ int flagBad, flagFloat;
    int tid = threadIdx.x;
    if (tid == 0) { flagBad = 0; flagFloat = 0; }
    __syncthreads();

    const unsigned* mw = (const unsigned*)mask_raw;
    for (int i = tid; i < 2401; i += blockDim.x) {
        unsigned w = mw[i];
        if (w != 0u && w != 1u && w != 0x3F800000u) flagBad = 1;
        if (w == 0x3F800000u) flagFloat = 1;
    }
    __syncthreads();
    int mode = flagBad ? 2 : (flagFloat ? 1 : 0);  // 2=u8, 1=f32, 0=i32

    const unsigned char* m8 = (const unsigned char*)mask_raw;
    const float* mf = (const float*)mask_raw;
    const int*   mi = (const int*)mask_raw;

    for (int idx = tid; idx < NWMASK * LTOK; idx += blockDim.x) {
        int w = idx / LTOK, i = idx % LTOK;
        unsigned long long bits = 0ull;
        for (int j = 0; j < LTOK; j++) {
            int g = (w * LTOK + i) * LTOK + j;
            bool v = (mode == 2) ? (m8[g] != 0)
                   : (mode == 1) ? (mf[g] != 0.0f)
                                 : (mi[g] != 0);
            if (v) bits |= (1ull << j);
        }
        g_maskbits[idx] = bits;
    }

    for (int idx = tid; idx < HEADS * LTOK * LTOK; idx += blockDim.x) {
        int h = idx / (LTOK * LTOK);
        int ij = idx % (LTOK * LTOK);
        g_bias[idx] = rel_bias[rel_coords[ij] * HEADS + h];
    }
}

// ---------------------------------------------------------------------------
// SGEMM (TN): C[M][N] = A[M][K] * B[N][K]^T (+ bias[n])
// BM=BN=128, BK=8, 256 threads, 8x8 microtile, register prefetch.
// M, N multiples of 128; K multiple of 8 (no bounds checks needed here).
// ---------------------------------------------------------------------------
__global__ __launch_bounds__(256, 2)
void sgemm_tn(const float* __restrict__ A, const float* __restrict__ B,
              const float* __restrict__ bias, float* __restrict__ C,
              int N, int K)
{
    __shared__ __align__(16) float sA[8 * 128];
    __shared__ __align__(16) float sB[8 * 128];

    const int t = threadIdx.x;
    const int ldRow = t >> 1;           // 0..127
    const int ldCol = (t & 1) << 2;     // 0 or 4
    const int tx = t & 15;              // col group
    const int ty = t >> 4;              // row group

    const int m0 = blockIdx.y * 128;
    const int n0 = blockIdx.x * 128;

    const float* Aptr = A + (size_t)(m0 + ldRow) * K + ldCol;
    const float* Bptr = B + (size_t)(n0 + ldRow) * K + ldCol;

    float acc[8][8];
#pragma unroll
    for (int i = 0; i < 8; i++)
#pragma unroll
        for (int j = 0; j < 8; j++) acc[i][j] = 0.0f;

    const int nTiles = K >> 3;  // 48

    // preload tile 0
    float4 pa = *(const float4*)Aptr;
    float4 pb = *(const float4*)Bptr;
    sA[(ldCol + 0) * 128 + ldRow] = pa.x;
    sA[(ldCol + 1) * 128 + ldRow] = pa.y;
    sA[(ldCol + 2) * 128 + ldRow] = pa.z;
    sA[(ldCol + 3) * 128 + ldRow] = pa.w;
    sB[(ldCol + 0) * 128 + ldRow] = pb.x;
    sB[(ldCol + 1) * 128 + ldRow] = pb.y;
    sB[(ldCol + 2) * 128 + ldRow] = pb.z;
    sB[(ldCol + 3) * 128 + ldRow] = pb.w;
    __syncthreads();

    for (int kt = 0; kt < nTiles; kt++) {
        if (kt + 1 < nTiles) {
            pa = *(const float4*)(Aptr + (kt + 1) * 8);
            pb = *(const float4*)(Bptr + (kt + 1) * 8);
        }
#pragma unroll
        for (int kk = 0; kk < 8; kk++) {
            float af[8], bf[8];
            const float* Ap = &sA[kk * 128 + ty * 8];
            const float* Bp = &sB[kk * 128 + tx * 8];
            float4 a0 = *(const float4*)(Ap);
            float4 a1 = *(const float4*)(Ap + 4);
            float4 b0 = *(const float4*)(Bp);
            float4 b1 = *(const float4*)(Bp + 4);
            af[0]=a0.x; af[1]=a0.y; af[2]=a0.z; af[3]=a0.w;
            af[4]=a1.x; af[5]=a1.y; af[6]=a1.z; af[7]=a1.w;
            bf[0]=b0.x; bf[1]=b0.y; bf[2]=b0.z; bf[3]=b0.w;
            bf[4]=b1.x; bf[5]=b1.y; bf[6]=b1.z; bf[7]=b1.w;
#pragma unroll
            for (int i = 0; i < 8; i++)
#pragma unroll
                for (int j = 0; j < 8; j++)
                    acc[i][j] = fmaf(af[i], bf[j], acc[i][j]);
        }
        __syncthreads();
        if (kt + 1 < nTiles) {
            sA[(ldCol + 0) * 128 + ldRow] = pa.x;
            sA[(ldCol + 1) * 128 + ldRow] = pa.y;
            sA[(ldCol + 2) * 128 + ldRow] = pa.z;
            sA[(ldCol + 3) * 128 + ldRow] = pa.w;
            sB[(ldCol + 0) * 128 + ldRow] = pb.x;
            sB[(ldCol + 1) * 128 + ldRow] = pb.y;
            sB[(ldCol + 2) * 128 + ldRow] = pb.z;
            sB[(ldCol + 3) * 128 + ldRow] = pb.w;
            __syncthreads();
        }
    }

    float bb[8];
#pragma unroll
    for (int j = 0; j < 8; j++)
        bb[j] = bias ? bias[n0 + tx * 8 + j] : 0.0f;

#pragma unroll
    for (int i = 0; i < 8; i++) {
        float* Crow = C + (size_t)(m0 + ty * 8 + i) * N + n0 + tx * 8;
        float4 c0, c1;
        c0.x = acc[i][0] + bb[0]; c0.y = acc[i][1] + bb[1];
        c0.z = acc[i][2] + bb[2]; c0.w = acc[i][3] + bb[3];
        c1.x = acc[i][4] + bb[4]; c1.y = acc[i][5] + bb[5];
        c1.z = acc[i][6] + bb[6]; c1.w = acc[i][7] + bb[7];
        *(float4*)(Crow)     = c0;
        *(float4*)(Crow + 4) = c1;
    }
}

// ---------------------------------------------------------------------------
// Fused window attention: one block per (b, h). 128 threads (4 warps).
// Warp-per-query-row: lanes cover keys j and j+32; softmax via warp shuffles;
// AV with lane = head-dim.
// ---------------------------------------------------------------------------
__global__ __launch_bounds__(128)
void attn_kernel(const float* __restrict__ qkv, float* __restrict__ o)
{
    const int h = blockIdx.x;
    const int b = blockIdx.y;
    const int tid = threadIdx.x;

    __shared__ __align__(16) float qs[LTOK * 33];
    __shared__ __align__(16) float ks[LTOK * 33];
    __shared__ __align__(16) float vs[LTOK * 33];
    __shared__ float bs[LTOK * LTOK];
    __shared__ float prow[4][64];

    const float* base = qkv + (size_t)(b * LTOK) * QKVN + h * HD;
    for (int tIdx = tid; tIdx < LTOK * HD; tIdx += 128) {
        int l = tIdx >> 5, d = tIdx & 31;
        qs[l * 33 + d] = base[(size_t)l * QKVN + d];
        ks[l * 33 + d] = base[(size_t)l * QKVN + CDIM + d];
        vs[l * 33 + d] = base[(size_t)l * QKVN + 2 * CDIM + d];
    }
    for (int tIdx = tid; tIdx < LTOK * LTOK; tIdx += 128)
        bs[tIdx] = g_bias[h * LTOK * LTOK + tIdx];
    __syncthreads();

    const int warp = tid >> 5;
    const int lane = tid & 31;
    const bool valid1 = (lane + 32) < LTOK;   // lanes 0..16 have a second key
    const int j2 = valid1 ? lane + 32 : 0;

    for (int i = warp; i < LTOK; i += 4) {
        unsigned long long mb = g_maskbits[(b & 3) * LTOK + i];

        float acc0 = 0.0f, acc1 = 0.0f;
#pragma unroll
        for (int d = 0; d < HD; d++) {
            float qv = qs[i * 33 + d];
            acc0 = fmaf(qv, ks[lane * 33 + d], acc0);
            acc1 = fmaf(qv, ks[j2 * 33 + d], acc1);
        }
        float x0 = acc0 * SCALE_F + bs[i * LTOK + lane];
        if ((mb >> lane) & 1ull) x0 = -100.0f;
        float x1 = -3.0e38f;
        if (valid1) {
            x1 = acc1 * SCALE_F + bs[i * LTOK + lane + 32];
            if ((mb >> (lane + 32)) & 1ull) x1 = -100.0f;
        }

        float mx = fmaxf(x0, x1);
#pragma unroll
        for (int off = 16; off; off >>= 1)
            mx = fmaxf(mx, __shfl_xor_sync(0xFFFFFFFFu, mx, off));

        float e0 = __expf(x0 - mx);
        float e1 = valid1 ? __expf(x1 - mx) : 0.0f;
        float s = e0 + e1;
#pragma unroll
        for (int off = 16; off; off >>= 1)
            s += __shfl_xor_sync(0xFFFFFFFFu, s, off);
        float inv = 1.0f / s;

        prow[warp][lane] = e0 * inv;
        if (valid1) prow[warp][lane + 32] = e1 * inv;
        __syncwarp();

        // AV: lane = head-dim
        float out = 0.0f;
#pragma unroll
        for (int j = 0; j < LTOK; j++)
            out = fmaf(prow[warp][j], vs[j * 33 + lane], out);

        o[(size_t)(b * LTOK + i) * CDIM + h * HD + lane] = out;
        __syncwarp();
    }
}

// ---------------------------------------------------------------------------
// Launch
// ---------------------------------------------------------------------------
extern "C" void kernel_launch(void* const* d_in, const int* in_sizes, int n_in,
                              void* d_out, int out_size)
{
    const float* x          = (const float*)d_in[0];
    const void*  mask       = d_in[1];
    const float* qkv_w      = (const float*)d_in[2];
    const float* proj_w     = (const float*)d_in[3];
    const float* proj_b     = (const float*)d_in[4];
    const float* rel_bias   = (const float*)d_in[5];
    const int*   rel_coords = (const int*)d_in[6];
    float* out = (float*)d_out;

    float* qkv_s;  cudaGetSymbolAddress((void**)&qkv_s, g_qkv);
    float* o_s;    cudaGetSymbolAddress((void**)&o_s, g_o);

    prep_kernel<<<1, 1024>>>(mask, rel_bias, rel_coords);

    // QKV = x @ qkv_w^T   (M=50176, N=1152, K=384)
    {
        dim3 grid(QKVN / 128, MTOT / 128);
        sgemm_tn<<<grid, 256>>>(x, qkv_w, nullptr, qkv_s, QKVN, CDIM);
    }

    // attention per (b, h)
    {
        dim3 grid(HEADS, B_WIN);
        attn_kernel<<<grid, 128>>>(qkv_s, o_s);
    }

    // out = O @ proj_w^T + proj_b   (M=50176, N=384, K=384)
    {
        dim3 grid(CDIM / 128, MTOT / 128);
        sgemm_tn<<<grid, 256>>>(o_s, proj_w, proj_b, out, CDIM, CDIM);
    }
}

// round 5
// speedup vs baseline: 1.2892x; 1.2892x over previous
#include <cuda_runtime.h>
#include <cuda_bf16.h>
#include <cstdint>

// Problem constants
#define B_WIN   1024
#define LTOK    49
#define CDIM    384
#define HEADS   12
#define HD      32
#define NWMASK  4
#define MTOT    (B_WIN * LTOK)          // 50176
#define QKVN    (3 * CDIM)              // 1152
#define KSPL    (3 * CDIM)              // 1152: [hi,lo,hi] x [hi,hi,lo] 3-term split
#define SCALE_F 19.595917942265426f     // sqrt(384)

// GEMM tiling (mma.sync bf16 path; tcgen05 unavailable on compute_103 PTX target)
#define BM 128
#define BN 128
#define BK 32
#define ROWB 80                          // 32 bf16 = 64B + 16B pad (conflict-free ldmatrix)
#define OPBYTES (128 * ROWB)             // 10240 per operand per stage
#define STG (2 * OPBYTES)                // 20480
#define DEPTH 3
#define NS (KSPL / BK)                   // 36
#define GSMEM (DEPTH * STG)              // 61440

// Scratch (device globals, allocation-free)
__device__ __align__(16) float          g_qkv[(size_t)MTOT * QKVN];   // 231 MB
__device__ __align__(16) __nv_bfloat16  g_a1[(size_t)MTOT * KSPL];    // 116 MB
__device__ __align__(16) __nv_bfloat16  g_a2[(size_t)MTOT * KSPL];    // 116 MB
__device__ __align__(16) __nv_bfloat16  g_b1[(size_t)QKVN * KSPL];    // 2.6 MB
__device__ __align__(16) __nv_bfloat16  g_b2[(size_t)CDIM * KSPL];    // 0.9 MB
__device__ __align__(16) float g_bias[HEADS * LTOK * LTOK];
__device__ unsigned long long g_maskbits[NWMASK * LTOK];

// ---------------------------------------------------------------------------
// Helpers
// ---------------------------------------------------------------------------
__device__ __forceinline__ uint32_t smem_u32(const void* p) {
    uint32_t a;
    asm("{ .reg .u64 t; cvta.to.shared.u64 t, %1; cvt.u32.u64 %0, t; }" : "=r"(a) : "l"(p));
    return a;
}
__device__ __forceinline__ void cp16(uint32_t dst, const void* src) {
    asm volatile("cp.async.cg.shared.global [%0], [%1], 16;" :: "r"(dst), "l"(src) : "memory");
}
__device__ __forceinline__ void cp_commit() { asm volatile("cp.async.commit_group;" ::: "memory"); }
template <int N> __device__ __forceinline__ void cp_wait() {
    asm volatile("cp.async.wait_group %0;" :: "n"(N) : "memory");
}
#define LDSM_X4(r0, r1, r2, r3, addr) \
    asm volatile("ldmatrix.sync.aligned.m8n8.x4.shared.b16 {%0,%1,%2,%3}, [%4];" \
                 : "=r"(r0), "=r"(r1), "=r"(r2), "=r"(r3) : "r"(addr))

__device__ __forceinline__ void mma16816(float* d, const uint32_t* a, const uint32_t* b) {
    asm volatile("mma.sync.aligned.m16n8k16.row.col.f32.bf16.bf16.f32 "
        "{%0,%1,%2,%3}, {%4,%5,%6,%7}, {%8,%9}, {%0,%1,%2,%3};"
        : "+f"(d[0]), "+f"(d[1]), "+f"(d[2]), "+f"(d[3])
        : "r"(a[0]), "r"(a[1]), "r"(a[2]), "r"(a[3]), "r"(b[0]), "r"(b[1]));
}

// ---------------------------------------------------------------------------
// Prep: mask dtype detect + bitmask pack + bias gather (validated in R2)
// ---------------------------------------------------------------------------
__global__ void prep_kernel(const void* __restrict__ mask_raw,
                            const float* __restrict__ rel_bias,
                            const int* __restrict__ rel_coords)
{
    __shared__ int flagBad, flagFloat;
    int tid = threadIdx.x;
    if (tid == 0) { flagBad = 0; flagFloat = 0; }
    __syncthreads();

    const unsigned* mw = (const unsigned*)mask_raw;
    for (int i = tid; i < 2401; i += blockDim.x) {
        unsigned w = mw[i];
        if (w != 0u && w != 1u && w != 0x3F800000u) flagBad = 1;
        if (w == 0x3F800000u) flagFloat = 1;
    }
    __syncthreads();
    int mode = flagBad ? 2 : (flagFloat ? 1 : 0);

    const unsigned char* m8 = (const unsigned char*)mask_raw;
    const float* mf = (const float*)mask_raw;
    const int*   mi = (const int*)mask_raw;

    for (int idx = tid; idx < NWMASK * LTOK; idx += blockDim.x) {
        int w = idx / LTOK, i = idx % LTOK;
        unsigned long long bits = 0ull;
        for (int j = 0; j < LTOK; j++) {
            int g = (w * LTOK + i) * LTOK + j;
            bool v = (mode == 2) ? (m8[g] != 0)
                   : (mode == 1) ? (mf[g] != 0.0f)
                                 : (mi[g] != 0);
            if (v) bits |= (1ull << j);
        }
        g_maskbits[idx] = bits;
    }
    for (int idx = tid; idx < HEADS * LTOK * LTOK; idx += blockDim.x) {
        int h = idx / (LTOK * LTOK);
        int ij = idx % (LTOK * LTOK);
        g_bias[idx] = rel_bias[rel_coords[ij] * HEADS + h];
    }
}

// ---------------------------------------------------------------------------
// bf16 3-term split.  A: [hi, lo, hi]   B: [hi, hi, lo]
// sum over 3 K-blocks = hi*hi + lo*hi + hi*lo (lo*lo ~2^-18 dropped)
// ---------------------------------------------------------------------------
__global__ void split_a_kernel(const float* __restrict__ src,
                               __nv_bfloat16* __restrict__ dst, int total)
{
    int idx = blockIdx.x * blockDim.x + threadIdx.x;
    if (idx >= total) return;
    int r = idx / CDIM, c = idx % CDIM;
    float v = src[idx];
    __nv_bfloat16 hi = __float2bfloat16(v);
    __nv_bfloat16 lo = __float2bfloat16(v - __bfloat162float(hi));
    size_t base = (size_t)r * KSPL;
    dst[base + c]            = hi;
    dst[base + CDIM + c]     = lo;
    dst[base + 2 * CDIM + c] = hi;
}
__global__ void split_b_kernel(const float* __restrict__ src,
                               __nv_bfloat16* __restrict__ dst, int total)
{
    int idx = blockIdx.x * blockDim.x + threadIdx.x;
    if (idx >= total) return;
    int r = idx / CDIM, c = idx % CDIM;
    float v = src[idx];
    __nv_bfloat16 hi = __float2bfloat16(v);
    __nv_bfloat16 lo = __float2bfloat16(v - __bfloat162float(hi));
    size_t base = (size_t)r * KSPL;
    dst[base + c]            = hi;
    dst[base + CDIM + c]     = hi;
    dst[base + 2 * CDIM + c] = lo;
}

// ---------------------------------------------------------------------------
// mma.sync bf16 GEMM (TN): C[m][n] = sum_k A[m][k]*B[n][k] (+bias[n])
// 128x128 tile, BK=32, 8 warps (4x2), warp tile 32x64, cp.async 3-stage.
// ---------------------------------------------------------------------------
__global__ __launch_bounds__(256, 2)
void gemm_mma(const __nv_bfloat16* __restrict__ A, const __nv_bfloat16* __restrict__ B,
              const float* __restrict__ bias, float* __restrict__ C, int N)
{
    extern __shared__ __align__(16) char smem[];
    const uint32_t sb = smem_u32(smem);
    const int tid = threadIdx.x;
    const int lane = tid & 31, warp = tid >> 5;
    const int wr = warp >> 1, wc = warp & 1;
    const int m0 = blockIdx.y * BM, n0 = blockIdx.x * BN;

    const __nv_bfloat16* Ab = A + (size_t)m0 * KSPL;
    const __nv_bfloat16* Bb = B + (size_t)n0 * KSPL;

    // loader coords: e = tid + i*256; row = e&127, c16 = e>>7
    const int lrow  = tid & 127;
    const int lc16a = tid >> 7;

    auto load_stage = [&](int st) {
        uint32_t buf = sb + (st % DEPTH) * STG;
        int kc = st * BK;
#pragma unroll
        for (int i = 0; i < 2; i++) {
            int c16 = lc16a + i * 2;
            uint32_t d = buf + lrow * ROWB + c16 * 16;
            const __nv_bfloat16* s = Ab + (size_t)lrow * KSPL + kc + c16 * 8;
            cp16(d, s);
            cp16(d + OPBYTES, Bb + (size_t)lrow * KSPL + kc + c16 * 8);
        }
        cp_commit();
    };

    float acc[2][8][4];
#pragma unroll
    for (int mt = 0; mt < 2; mt++)
#pragma unroll
        for (int j = 0; j < 8; j++)
#pragma unroll
            for (int q = 0; q < 4; q++) acc[mt][j][q] = 0.0f;

    load_stage(0);
    load_stage(1);

    // ldmatrix per-lane byte offsets
    // A x4 matrices: [m0-7,kl],[m8-15,kl],[m0-7,kh],[m8-15,kh]
    const uint32_t a_lane = (uint32_t)((wr * 32 + ((lane >> 3) & 1) * 8 + (lane & 7)) * ROWB
                                       + (lane >> 4) * 16);
    // B x4 matrices: [n0-7,kl],[n0-7,kh],[n8-15,kl],[n8-15,kh]
    const uint32_t b_lane = (uint32_t)(OPBYTES
                                       + (wc * 64 + ((lane >> 4) & 1) * 8 + (lane & 7)) * ROWB
                                       + ((lane >> 3) & 1) * 16);

    for (int s = 0; s < NS; s++) {
        if (s == NS - 1) cp_wait<0>(); else cp_wait<1>();
        __syncthreads();
        if (s + 2 < NS) load_stage(s + 2);

        uint32_t buf = sb + (s % DEPTH) * STG;
#pragma unroll
        for (int ks = 0; ks < 2; ks++) {
            uint32_t ra[2][4];
#pragma unroll
            for (int mt = 0; mt < 2; mt++)
                LDSM_X4(ra[mt][0], ra[mt][1], ra[mt][2], ra[mt][3],
                        buf + a_lane + mt * 16 * ROWB + ks * 32);
            uint32_t rb[8][2];
#pragma unroll
            for (int nt = 0; nt < 4; nt++) {
                uint32_t r0, r1, r2, r3;
                LDSM_X4(r0, r1, r2, r3, buf + b_lane + nt * 16 * ROWB + ks * 32);
                rb[2 * nt][0] = r0; rb[2 * nt][1] = r1;
                rb[2 * nt + 1][0] = r2; rb[2 * nt + 1][1] = r3;
            }
#pragma unroll
            for (int mt = 0; mt < 2; mt++)
#pragma unroll
                for (int j = 0; j < 8; j++)
                    mma16816(acc[mt][j], ra[mt], rb[j]);
        }
    }

    // epilogue
    const int g = lane >> 2, tq = lane & 3;
#pragma unroll
    for (int mt = 0; mt < 2; mt++) {
        int r0 = m0 + wr * 32 + mt * 16 + g;
#pragma unroll
        for (int j = 0; j < 8; j++) {
            int c0 = n0 + wc * 64 + j * 8 + 2 * tq;
            float2 v0 = make_float2(acc[mt][j][0], acc[mt][j][1]);
            float2 v1 = make_float2(acc[mt][j][2], acc[mt][j][3]);
            if (bias) {
                float b0 = bias[c0], b1 = bias[c0 + 1];
                v0.x += b0; v0.y += b1; v1.x += b0; v1.y += b1;
            }
            *(float2*)(C + (size_t)r0 * N + c0)       = v0;
            *(float2*)(C + (size_t)(r0 + 8) * N + c0) = v1;
        }
    }
}

// ---------------------------------------------------------------------------
// Fused window attention (validated in R2); writes bf16 3-term split output
// directly into the proj-GEMM A operand ([hi, lo, hi]).
// ---------------------------------------------------------------------------
__global__ __launch_bounds__(128)
void attn_kernel(const float* __restrict__ qkv, __nv_bfloat16* __restrict__ a2)
{
    const int h = blockIdx.x;
    const int b = blockIdx.y;
    const int tid = threadIdx.x;

    __shared__ __align__(16) float qs[LTOK * 33];
    __shared__ __align__(16) float ks[LTOK * 33];
    __shared__ __align__(16) float vs[LTOK * 33];
    __shared__ float bs[LTOK * LTOK];
    __shared__ float prow[4][64];

    const float* base = qkv + (size_t)(b * LTOK) * QKVN + h * HD;
    for (int tIdx = tid; tIdx < LTOK * HD; tIdx += 128) {
        int l = tIdx >> 5, d = tIdx & 31;
        qs[l * 33 + d] = base[(size_t)l * QKVN + d];
        ks[l * 33 + d] = base[(size_t)l * QKVN + CDIM + d];
        vs[l * 33 + d] = base[(size_t)l * QKVN + 2 * CDIM + d];
    }
    for (int tIdx = tid; tIdx < LTOK * LTOK; tIdx += 128)
        bs[tIdx] = g_bias[h * LTOK * LTOK + tIdx];
    __syncthreads();

    const int warp = tid >> 5;
    const int lane = tid & 31;
    const bool valid1 = (lane + 32) < LTOK;
    const int j2 = valid1 ? lane + 32 : 0;

    for (int i = warp; i < LTOK; i += 4) {
        unsigned long long mb = g_maskbits[(b & 3) * LTOK + i];

        float acc0 = 0.0f, acc1 = 0.0f;
#pragma unroll
        for (int d = 0; d < HD; d++) {
            float qv = qs[i * 33 + d];
            acc0 = fmaf(qv, ks[lane * 33 + d], acc0);
            acc1 = fmaf(qv, ks[j2 * 33 + d], acc1);
        }
        float x0 = acc0 * SCALE_F + bs[i * LTOK + lane];
        if ((mb >> lane) & 1ull) x0 = -100.0f;
        float x1 = -3.0e38f;
        if (valid1) {
            x1 = acc1 * SCALE_F + bs[i * LTOK + lane + 32];
            if ((mb >> (lane + 32)) & 1ull) x1 = -100.0f;
        }

        float mx = fmaxf(x0, x1);
#pragma unroll
        for (int off = 16; off; off >>= 1)
            mx = fmaxf(mx, __shfl_xor_sync(0xFFFFFFFFu, mx, off));

        float e0 = __expf(x0 - mx);
        float e1 = valid1 ? __expf(x1 - mx) : 0.0f;
        float s = e0 + e1;
#pragma unroll
        for (int off = 16; off; off >>= 1)
            s += __shfl_xor_sync(0xFFFFFFFFu, s, off);
        float inv = 1.0f / s;

        prow[warp][lane] = e0 * inv;
        if (valid1) prow[warp][lane + 32] = e1 * inv;
        __syncwarp();

        float out = 0.0f;
#pragma unroll
        for (int j = 0; j < LTOK; j++)
            out = fmaf(prow[warp][j], vs[j * 33 + lane], out);

        __nv_bfloat16 hi = __float2bfloat16(out);
        __nv_bfloat16 lo = __float2bfloat16(out - __bfloat162float(hi));
        size_t rb = (size_t)(b * LTOK + i) * KSPL + h * HD + lane;
        a2[rb]            = hi;
        a2[rb + CDIM]     = lo;
        a2[rb + 2 * CDIM] = hi;
        __syncwarp();
    }
}

// ---------------------------------------------------------------------------
// Launch
// ---------------------------------------------------------------------------
extern "C" void kernel_launch(void* const* d_in, const int* in_sizes, int n_in,
                              void* d_out, int out_size)
{
    const float* x          = (const float*)d_in[0];
    const void*  mask       = d_in[1];
    const float* qkv_w      = (const float*)d_in[2];
    const float* proj_w     = (const float*)d_in[3];
    const float* proj_b     = (const float*)d_in[4];
    const float* rel_bias   = (const float*)d_in[5];
    const int*   rel_coords = (const int*)d_in[6];
    float* out = (float*)d_out;

    float* qkv_s;          cudaGetSymbolAddress((void**)&qkv_s, g_qkv);
    __nv_bfloat16* a1_s;   cudaGetSymbolAddress((void**)&a1_s, g_a1);
    __nv_bfloat16* a2_s;   cudaGetSymbolAddress((void**)&a2_s, g_a2);
    __nv_bfloat16* b1_s;   cudaGetSymbolAddress((void**)&b1_s, g_b1);
    __nv_bfloat16* b2_s;   cudaGetSymbolAddress((void**)&b2_s, g_b2);

    cudaFuncSetAttribute(gemm_mma, cudaFuncAttributeMaxDynamicSharedMemorySize, GSMEM);

    prep_kernel<<<1, 1024>>>(mask, rel_bias, rel_coords);

    split_a_kernel<<<(MTOT * CDIM + 255) / 256, 256>>>(x, a1_s, MTOT * CDIM);
    split_b_kernel<<<(QKVN * CDIM + 255) / 256, 256>>>(qkv_w, b1_s, QKVN * CDIM);
    split_b_kernel<<<(CDIM * CDIM + 255) / 256, 256>>>(proj_w, b2_s, CDIM * CDIM);

    // QKV = x @ qkv_w^T  (M=50176, N=1152, K_eff=1152)
    {
        dim3 grid(QKVN / BN, MTOT / BM);
        gemm_mma<<<grid, 256, GSMEM>>>(a1_s, b1_s, nullptr, qkv_s, QKVN);
    }

    // attention, writing split output directly
    {
        dim3 grid(HEADS, B_WIN);
        attn_kernel<<<grid, 128>>>(qkv_s, a2_s);
    }

    // out = O @ proj_w^T + proj_b  (M=50176, N=384, K_eff=1152)
    {
        dim3 grid(CDIM / BN, MTOT / BM);
        gemm_mma<<<grid, 256, GSMEM>>>(a2_s, b2_s, proj_b, out, CDIM);
    }
}